// round 10
// baseline (speedup 1.0000x reference)
#include <cuda_runtime.h>

// ---- problem constants ----
#define BB 64
#define NN 128
#define TT 16
#define NUM_CLS 600
#define MAX_H 15
#define MAX_O 15
#define NMAX 30
#define MM 450            // MAX_H * NMAX
#define HUMAN_IDX 49
#define SCORE_TH 0.2f
#define NMS_TH 0.5f
#define PEXP 2.8f

#define BM (BB * MM)      // 28800

// float offsets in the flattened output (tuple order, all f32)
#define OFF_BH   0                      // boxes_h  [B,M,4]
#define OFF_BO   115200                 // boxes_o  [B,M,4]
#define OFF_CLS  230400                 // obj_cls  [B,M]
#define OFF_LAB  259200                 // lab_gt   [B,M,600]
#define OFF_PRI  17539200               // prior    [B,2,M,600]
#define OFF_PV   52099200               // pv       [B,M]

#define NROWS    86400                  // 28800 lab rows + 57600 pri rows
#define K2_BLOCKS 1184                  // 8 per SM, one wave
#define ZB (K2_BLOCKS - BB)             // zero-only blocks
#define ZWARPS (ZB * 8)

// compact per-image valid-pair lists (select -> expand)
__device__ uint4 g_list[BB][440];       // {m | mask<<16, cls, sh, so}
__device__ int   g_cnt[BB];
__device__ unsigned g_vbits[BB * 15];   // per-image 450-bit pair-validity mask

// IoU(a,b) > th  without division (denominator strictly positive)
__device__ __forceinline__ bool iou_gt(float4 a, float4 b, float th) {
    float area_a = (a.z - a.x) * (a.w - a.y);
    float area_b = (b.z - b.x) * (b.w - b.y);
    float w = fmaxf(fminf(a.z, b.z) - fmaxf(a.x, b.x), 0.0f);
    float h = fmaxf(fminf(a.w, b.w) - fmaxf(a.y, b.y), 0.0f);
    float inter = w * h;
    return inter > th * (area_a + area_b - inter + 1e-7f);
}
__device__ __forceinline__ bool iou_ge(float4 a, float4 b, float th) {
    float area_a = (a.z - a.x) * (a.w - a.y);
    float area_b = (b.z - b.x) * (b.w - b.y);
    float w = fmaxf(fminf(a.z, b.z) - fmaxf(a.x, b.x), 0.0f);
    float h = fmaxf(fminf(a.w, b.w) - fmaxf(a.y, b.y), 0.0f);
    float inter = w * h;
    return inter >= th * (area_a + area_b - inter + 1e-7f);
}

// ============================================================
// Kernel 1: selection only. One 512-thread block per image.
// ============================================================
__global__ __launch_bounds__(512, 1)
void pairgen_select_kernel(const float* __restrict__ boxes,
                           const float* __restrict__ scores,
                           const int*   __restrict__ labels,
                           const float* __restrict__ tbh,
                           const float* __restrict__ tbo,
                           float* __restrict__ out) {
    __shared__ float4 sb[NN];
    __shared__ float  ss[NN];
    __shared__ int    sl[NN];
    __shared__ uint4  predm[NN];
    __shared__ uint4  higher[NN];
    __shared__ unsigned int validw[4], ishw[4];
    __shared__ unsigned int kw[2][4];
    __shared__ int    sch[2];
    __shared__ float4 coords[NMAX];
    __shared__ int    labp[NMAX];
    __shared__ float  scp[NMAX];
    __shared__ int    s_nh, s_nt, s_cnt;
    __shared__ float4 stbh[TT], stbo[TT];
    __shared__ unsigned int mbits_h[NMAX], mbits_o[NMAX];
    __shared__ float  pw[NMAX];

    const int b    = blockIdx.x;
    const int tid  = threadIdx.x;
    const int wid  = tid >> 5;
    const int lane = tid & 31;

    if (tid < NN) {
        sb[tid] = ((const float4*)boxes)[b * NN + tid];
        ss[tid] = scores[b * NN + tid];
        sl[tid] = labels[b * NN + tid];
    } else if (tid < NN + TT) {
        const int t = tid - NN;
        stbh[t] = ((const float4*)tbh)[b * TT + t];
        stbo[t] = ((const float4*)tbo)[b * TT + t];
    }
    if (tid == 0) { s_cnt = 0; sch[0] = 0; sch[1] = 0; }
    __syncthreads();

    if (wid == 0) {
        #pragma unroll
        for (int k = 0; k < 4; k++) {
            const int j = lane + 32 * k;
            const unsigned v = __ballot_sync(0xffffffffu, ss[j] >= SCORE_TH);
            const unsigned h = __ballot_sync(0xffffffffu, sl[j] == HUMAN_IDX);
            if (lane == 0) { validw[k] = v; ishw[k] = h; }
        }
    }

    // ---- phase 2: higher-rank + suppression-pred masks (warp per i) ----
    for (int i = wid; i < NN; i += 16) {
        const float4 bi = sb[i];
        const float  si = ss[i];
        const int    li = sl[i];
        const float  ki = (si >= SCORE_TH) ? si : -1.0f;
        unsigned hw[4], aw[4];
        #pragma unroll
        for (int k = 0; k < 4; k++) {
            const int j = lane + 32 * k;
            const float sj = ss[j];
            const float kj = (sj >= SCORE_TH) ? sj : -1.0f;
            hw[k] = __ballot_sync(0xffffffffu, (kj > ki) || (kj == ki && j < i));
            aw[k] = __ballot_sync(0xffffffffu,
                                  (sl[j] == li) && iou_gt(bi, sb[j], NMS_TH));
        }
        if (lane == 0) {
            higher[i] = make_uint4(hw[0], hw[1], hw[2], hw[3]);
            predm[i]  = make_uint4(hw[0] & aw[0], hw[1] & aw[1],
                                   hw[2] & aw[2], hw[3] & aw[3]);
        }
    }
    __syncthreads();

    // ---- phase 3: NMS fixed-point (exact greedy solution on DAG) ----
    if (tid < 4) kw[0][tid] = validw[tid];
    __syncthreads();
    int cur = 0;
    for (int round = 0; round < NN; round++) {
        if (tid == 0) sch[cur ^ 1] = 0;
        __syncthreads();
        bool nk = false;
        if (tid < NN) {
            const uint4 p = predm[tid];
            const unsigned s = (p.x & kw[cur][0]) | (p.y & kw[cur][1])
                             | (p.z & kw[cur][2]) | (p.w & kw[cur][3]);
            nk = ((validw[tid >> 5] >> (tid & 31)) & 1u) && (s == 0u);
        }
        const unsigned bal = __ballot_sync(0xffffffffu, nk);
        if (tid < NN && lane == 0) {
            kw[cur ^ 1][wid] = bal;
            if (bal != kw[cur][wid]) sch[cur ^ 1] = 1;
        }
        __syncthreads();
        cur ^= 1;
        if (!sch[cur]) break;
    }

    // ---- phase 4: direct slot scatter from rank popcounts ----
    {
        const unsigned k0 = kw[cur][0], k1 = kw[cur][1],
                       k2 = kw[cur][2], k3 = kw[cur][3];
        if (tid == 0) {
            const int nhT = __popc(k0 & ishw[0]) + __popc(k1 & ishw[1])
                          + __popc(k2 & ishw[2]) + __popc(k3 & ishw[3]);
            const int noT = __popc(k0 & ~ishw[0]) + __popc(k1 & ~ishw[1])
                          + __popc(k2 & ~ishw[2]) + __popc(k3 & ~ishw[3]);
            const int nh = nhT < MAX_H ? nhT : MAX_H;
            const int no = noT < MAX_O ? noT : MAX_O;
            s_nh = nh; s_nt = nh + no;
        }
        if (tid < NN) {
            const int w = tid >> 5, p = tid & 31;
            if ((kw[cur][w] >> p) & 1u) {
                const bool ish_i = (ishw[w] >> p) & 1u;
                const uint4 h = higher[tid];
                int slot = -1;
                if (ish_i) {
                    const int rh = __popc(h.x & k0 & ishw[0]) + __popc(h.y & k1 & ishw[1])
                                 + __popc(h.z & k2 & ishw[2]) + __popc(h.w & k3 & ishw[3]);
                    if (rh < MAX_H) slot = rh;
                } else {
                    const int ro = __popc(h.x & k0 & ~ishw[0]) + __popc(h.y & k1 & ~ishw[1])
                                 + __popc(h.z & k2 & ~ishw[2]) + __popc(h.w & k3 & ~ishw[3]);
                    if (ro < MAX_O) {
                        const int nhT = __popc(k0 & ishw[0]) + __popc(k1 & ishw[1])
                                      + __popc(k2 & ishw[2]) + __popc(k3 & ishw[3]);
                        slot = (nhT < MAX_H ? nhT : MAX_H) + ro;
                    }
                }
                if (slot >= 0) {
                    coords[slot] = sb[tid];
                    labp[slot]   = sl[tid];
                    scp[slot]    = ss[tid];
                }
            }
        }
    }
    __syncthreads();

    const int nh = s_nh;
    const int nt = s_nt;

    // ---- phase 6: per-slot GT-match bitmasks and s^p ----
    if (tid < NMAX) {
        unsigned bh = 0, bo = 0;
        float pwv = 0.0f;
        if (tid < nt) {
            const float4 c = coords[tid];
            #pragma unroll
            for (int t = 0; t < TT; t++) {
                if (iou_ge(c, stbh[t], 0.5f)) bh |= (1u << t);
                if (iou_ge(c, stbo[t], 0.5f)) bo |= (1u << t);
            }
            pwv = __powf(scp[tid], PEXP);
        }
        mbits_h[tid] = bh;
        mbits_o[tid] = bo;
        pw[tid] = pwv;
    }
    __syncthreads();

    // ---- phase 7a: small outputs + compact lists + validity bitmask ----
    if (tid < 480) {            // warps 0..14 fully active (ballot needs all lanes)
        const int m = tid;
        const int x = m / NMAX;
        const int y = m - x * NMAX;
        const bool pv = (m < MM) && (x < nh) && (y < nt) && (x != y);
        const unsigned word = __ballot_sync(0xffffffffu, pv);
        if (lane == 0) g_vbits[b * 15 + wid] = word;
        if (m < MM) {
            float4 bh = make_float4(0.f, 0.f, 0.f, 0.f);
            float4 bo = bh;
            int cls = 0;
            if (pv) {
                bh = coords[x];
                bo = coords[y];
                cls = labp[y];
                const unsigned mask = mbits_h[x] & mbits_o[y];
                const int slot = atomicAdd(&s_cnt, 1);
                g_list[b][slot] = make_uint4((unsigned)m | (mask << 16),
                                             (unsigned)cls,
                                             __float_as_uint(pw[x]),
                                             __float_as_uint(pw[y]));
            }
            const int row = b * MM + m;
            ((float4*)(out + OFF_BH))[row] = bh;
            ((float4*)(out + OFF_BO))[row] = bo;
            (out + OFF_CLS)[row] = pv ? (float)cls : 0.0f;
            (out + OFF_PV)[row]  = pv ? 1.0f : 0.0f;
        }
    }
    __syncthreads();
    if (tid == 0) g_cnt[b] = s_cnt;
}

// ============================================================
// Kernel 2: blocks 0..63 = expansion of valid rows (full
// overwrite, hidden under the store stream); blocks 64.. =
// warp-per-row zero-fill with per-row smem-bitmask validity.
// ============================================================
__global__ __launch_bounds__(256, 8)
void pairgen_zexp_kernel(const int* __restrict__ gt_labels,
                         const float* __restrict__ mapping,
                         float* __restrict__ out) {
    const int blk  = blockIdx.x;
    const int tid  = threadIdx.x;
    const int wid  = tid >> 5;
    const int lane = tid & 31;

    // ---------------- expansion (blocks 0..63) ----------------
    if (blk < BB) {
        __shared__ int sgt[TT];
        __shared__ unsigned int bmp[8][20];
        if (tid < TT) sgt[tid] = gt_labels[blk * TT + tid];
        __syncthreads();

        const int cnt = g_cnt[blk];
        for (int k = wid; k < cnt; k += 8) {
            const uint4 e = g_list[blk][k];
            const int m = (int)(e.x & 0xffffu);
            const unsigned mask = e.x >> 16;
            const int cls = (int)e.y;
            const float sh = __uint_as_float(e.z);
            const float so = __uint_as_float(e.w);
            const int row = blk * MM + m;

            float4* lab = (float4*)(out + OFF_LAB) + (size_t)row * 150;
            float4* pr0 = (float4*)(out + OFF_PRI) + ((size_t)blk * 2 * MM + m) * 150;
            float4* pr1 = pr0 + (size_t)MM * 150;

            if (lane < 19) bmp[wid][lane] = 0;
            __syncwarp();
            if (lane < TT && ((mask >> lane) & 1u)) {
                const int c = sgt[lane];
                atomicOr(&bmp[wid][c >> 5], 1u << (c & 31));
            }
            __syncwarp();

            const float4* mr = (const float4*)(mapping + cls * NUM_CLS);
            for (int i = lane; i < 150; i += 32) {
                const float4 mv = mr[i];
                pr0[i] = make_float4(mv.x * sh, mv.y * sh, mv.z * sh, mv.w * sh);
                pr1[i] = make_float4(mv.x * so, mv.y * so, mv.z * so, mv.w * so);
                const int c = i * 4;
                float4 lv;
                lv.x = ((bmp[wid][(c + 0) >> 5] >> ((c + 0) & 31)) & 1u) ? 1.0f : 0.0f;
                lv.y = ((bmp[wid][(c + 1) >> 5] >> ((c + 1) & 31)) & 1u) ? 1.0f : 0.0f;
                lv.z = ((bmp[wid][(c + 2) >> 5] >> ((c + 2) & 31)) & 1u) ? 1.0f : 0.0f;
                lv.w = ((bmp[wid][(c + 3) >> 5] >> ((c + 3) & 31)) & 1u) ? 1.0f : 0.0f;
                lab[i] = lv;
            }
            __syncwarp();
        }
        return;
    }

    // ---------------- zero path (blocks 64..1183, warp per row) ----------------
    __shared__ unsigned svb[BB * 15];
    #pragma unroll
    for (int i = tid; i < BB * 15; i += 256) svb[i] = g_vbits[i];
    __syncthreads();

    const float4 z = make_float4(0.f, 0.f, 0.f, 0.f);
    const int wg = (blk - BB) * 8 + wid;

    for (int row = wg; row < NROWS; row += ZWARPS) {
        int b, m;
        size_t base;
        if (row < BM) {
            b = row / MM;
            m = row - b * MM;
            base = (size_t)OFF_LAB + (size_t)row * 600;
        } else {
            const int rr = row - BM;
            b = rr / (2 * MM);
            const int k = rr - b * (2 * MM);
            m = (k >= MM) ? (k - MM) : k;
            base = (size_t)OFF_PRI + (size_t)rr * 600;
        }
        if ((svb[b * 15 + (m >> 5)] >> (m & 31)) & 1u) continue;  // valid: expand owns it
        float4* p = (float4*)(out + base) + lane;
        // 150 float4 per row: 4 full lane-strided steps + 22-lane tail
        p[0] = z; p[32] = z; p[64] = z; p[96] = z;
        if (lane < 22) p[128] = z;
    }
}

extern "C" void kernel_launch(void* const* d_in, const int* in_sizes, int n_in,
                              void* d_out, int out_size) {
    const float* boxes     = (const float*)d_in[0];
    const float* scores    = (const float*)d_in[1];
    const int*   labels    = (const int*)  d_in[2];
    const float* t_boxes_h = (const float*)d_in[3];
    const float* t_boxes_o = (const float*)d_in[4];
    const int*   gt_labels = (const int*)  d_in[5];
    const float* mapping   = (const float*)d_in[6];
    float* out = (float*)d_out;

    pairgen_select_kernel<<<BB, 512>>>(boxes, scores, labels,
                                       t_boxes_h, t_boxes_o, out);
    pairgen_zexp_kernel<<<K2_BLOCKS, 256>>>(gt_labels, mapping, out);
}

// round 11
// speedup vs baseline: 1.1251x; 1.1251x over previous
#include <cuda_runtime.h>

// ---- problem constants ----
#define BB 64
#define NN 128
#define TT 16
#define NUM_CLS 600
#define MAX_H 15
#define MAX_O 15
#define NMAX 30
#define MM 450            // MAX_H * NMAX
#define HUMAN_IDX 49
#define SCORE_TH 0.2f
#define NMS_TH 0.5f
#define PEXP 2.8f

#define BM (BB * MM)      // 28800

// float offsets in the flattened output (tuple order, all f32)
#define OFF_BH   0                      // boxes_h  [B,M,4]
#define OFF_BO   115200                 // boxes_o  [B,M,4]
#define OFF_CLS  230400                 // obj_cls  [B,M]
#define OFF_LAB  259200                 // lab_gt   [B,M,600]
#define OFF_PRI  17539200               // prior    [B,2,M,600]
#define OFF_PV   52099200               // pv       [B,M]
// lab+pri are contiguous: zero the whole 51,840,000-float region flat
#define ZERO_N4  12960000

#define K1_BLOCKS 740                   // 5 per SM on 148 SMs = one wave
#define ZBLK (K1_BLOCKS - BB)           // 676 zero blocks
#define ZSTRIDE (ZBLK * 256)

// compact per-image valid-pair lists (select -> expand)
__device__ uint4 g_list[BB][440];       // {m | mask<<16, cls, sh, so}
__device__ int   g_cnt[BB];

// IoU(a,b) > th  without division (denominator strictly positive)
__device__ __forceinline__ bool iou_gt(float4 a, float4 b, float th) {
    float area_a = (a.z - a.x) * (a.w - a.y);
    float area_b = (b.z - b.x) * (b.w - b.y);
    float w = fmaxf(fminf(a.z, b.z) - fmaxf(a.x, b.x), 0.0f);
    float h = fmaxf(fminf(a.w, b.w) - fmaxf(a.y, b.y), 0.0f);
    float inter = w * h;
    return inter > th * (area_a + area_b - inter + 1e-7f);
}
__device__ __forceinline__ bool iou_ge(float4 a, float4 b, float th) {
    float area_a = (a.z - a.x) * (a.w - a.y);
    float area_b = (b.z - b.x) * (b.w - b.y);
    float w = fmaxf(fminf(a.z, b.z) - fmaxf(a.x, b.x), 0.0f);
    float h = fmaxf(fminf(a.w, b.w) - fmaxf(a.y, b.y), 0.0f);
    float inter = w * h;
    return inter >= th * (area_a + area_b - inter + 1e-7f);
}

// ============================================================
// Kernel 1 (fused): blocks [0,64) = per-image selection (256 thr,
// ballot NMS); blocks [64,740) = bare flat zero-fill of lab+pri.
// Select is hidden under the 31us store stream. Zero does NOT
// skip valid rows; K2 fully overwrites them afterwards.
// ============================================================
__global__ __launch_bounds__(256, 5)
void pairgen_fused_kernel(const float* __restrict__ boxes,
                          const float* __restrict__ scores,
                          const int*   __restrict__ labels,
                          const float* __restrict__ tbh,
                          const float* __restrict__ tbo,
                          float* __restrict__ out) {
    // ---------------- zero path (blocks 64..739) ----------------
    if (blockIdx.x >= BB) {
        float4* p = (float4*)(out + OFF_LAB);
        const float4 z = make_float4(0.f, 0.f, 0.f, 0.f);
        int i = (blockIdx.x - BB) * 256 + threadIdx.x;
        for (; i + 3 * ZSTRIDE < ZERO_N4; i += 4 * ZSTRIDE) {
            p[i] = z; p[i + ZSTRIDE] = z;
            p[i + 2 * ZSTRIDE] = z; p[i + 3 * ZSTRIDE] = z;
        }
        for (; i < ZERO_N4; i += ZSTRIDE) p[i] = z;
        return;
    }

    // ---------------- select path (blocks 0..63) ----------------
    __shared__ float4 sb[NN];
    __shared__ float  ss[NN];
    __shared__ int    sl[NN];
    __shared__ uint4  predm[NN];
    __shared__ uint4  higher[NN];
    __shared__ unsigned int validw[4], ishw[4];
    __shared__ unsigned int kw[2][4];
    __shared__ int    sch[2];
    __shared__ float4 coords[NMAX];
    __shared__ int    labp[NMAX];
    __shared__ float  scp[NMAX];
    __shared__ int    s_nh, s_nt, s_cnt;
    __shared__ float4 stbh[TT], stbo[TT];
    __shared__ unsigned int mbits_h[NMAX], mbits_o[NMAX];
    __shared__ float  pw[NMAX];

    const int b    = blockIdx.x;
    const int tid  = threadIdx.x;
    const int wid  = tid >> 5;
    const int lane = tid & 31;

    if (tid < NN) {
        sb[tid] = ((const float4*)boxes)[b * NN + tid];
        ss[tid] = scores[b * NN + tid];
        sl[tid] = labels[b * NN + tid];
    } else if (tid < NN + TT) {
        const int t = tid - NN;
        stbh[t] = ((const float4*)tbh)[b * TT + t];
        stbo[t] = ((const float4*)tbo)[b * TT + t];
    }
    if (tid == 0) { s_cnt = 0; sch[0] = 0; sch[1] = 0; }
    __syncthreads();

    if (wid == 0) {
        #pragma unroll
        for (int k = 0; k < 4; k++) {
            const int j = lane + 32 * k;
            const unsigned v = __ballot_sync(0xffffffffu, ss[j] >= SCORE_TH);
            const unsigned h = __ballot_sync(0xffffffffu, sl[j] == HUMAN_IDX);
            if (lane == 0) { validw[k] = v; ishw[k] = h; }
        }
    }

    // ---- phase 2: higher-rank + suppression-pred masks (warp per i) ----
    for (int i = wid; i < NN; i += 8) {
        const float4 bi = sb[i];
        const float  si = ss[i];
        const int    li = sl[i];
        const float  ki = (si >= SCORE_TH) ? si : -1.0f;
        unsigned hw[4], aw[4];
        #pragma unroll
        for (int k = 0; k < 4; k++) {
            const int j = lane + 32 * k;
            const float sj = ss[j];
            const float kj = (sj >= SCORE_TH) ? sj : -1.0f;
            hw[k] = __ballot_sync(0xffffffffu, (kj > ki) || (kj == ki && j < i));
            aw[k] = __ballot_sync(0xffffffffu,
                                  (sl[j] == li) && iou_gt(bi, sb[j], NMS_TH));
        }
        if (lane == 0) {
            higher[i] = make_uint4(hw[0], hw[1], hw[2], hw[3]);
            predm[i]  = make_uint4(hw[0] & aw[0], hw[1] & aw[1],
                                   hw[2] & aw[2], hw[3] & aw[3]);
        }
    }
    __syncthreads();

    // ---- phase 3: NMS fixed-point (exact greedy solution on DAG) ----
    if (tid < 4) kw[0][tid] = validw[tid];
    __syncthreads();
    int cur = 0;
    for (int round = 0; round < NN; round++) {
        if (tid == 0) sch[cur ^ 1] = 0;
        __syncthreads();
        if (tid < NN) {
            const uint4 p = predm[tid];
            const unsigned s = (p.x & kw[cur][0]) | (p.y & kw[cur][1])
                             | (p.z & kw[cur][2]) | (p.w & kw[cur][3]);
            const bool nk = ((validw[tid >> 5] >> (tid & 31)) & 1u) && (s == 0u);
            const unsigned bal = __ballot_sync(0xffffffffu, nk);
            if (lane == 0) {
                kw[cur ^ 1][wid] = bal;
                if (bal != kw[cur][wid]) sch[cur ^ 1] = 1;
            }
        }
        __syncthreads();
        cur ^= 1;
        if (!sch[cur]) break;
    }

    // ---- phase 4: direct slot scatter from rank popcounts ----
    {
        const unsigned k0 = kw[cur][0], k1 = kw[cur][1],
                       k2 = kw[cur][2], k3 = kw[cur][3];
        if (tid == 0) {
            const int nhT = __popc(k0 & ishw[0]) + __popc(k1 & ishw[1])
                          + __popc(k2 & ishw[2]) + __popc(k3 & ishw[3]);
            const int noT = __popc(k0 & ~ishw[0]) + __popc(k1 & ~ishw[1])
                          + __popc(k2 & ~ishw[2]) + __popc(k3 & ~ishw[3]);
            const int nh = nhT < MAX_H ? nhT : MAX_H;
            const int no = noT < MAX_O ? noT : MAX_O;
            s_nh = nh; s_nt = nh + no;
        }
        if (tid < NN) {
            const int w = tid >> 5, p = tid & 31;
            if ((kw[cur][w] >> p) & 1u) {
                const bool ish_i = (ishw[w] >> p) & 1u;
                const uint4 h = higher[tid];
                int slot = -1;
                if (ish_i) {
                    const int rh = __popc(h.x & k0 & ishw[0]) + __popc(h.y & k1 & ishw[1])
                                 + __popc(h.z & k2 & ishw[2]) + __popc(h.w & k3 & ishw[3]);
                    if (rh < MAX_H) slot = rh;
                } else {
                    const int ro = __popc(h.x & k0 & ~ishw[0]) + __popc(h.y & k1 & ~ishw[1])
                                 + __popc(h.z & k2 & ~ishw[2]) + __popc(h.w & k3 & ~ishw[3]);
                    if (ro < MAX_O) {
                        const int nhT = __popc(k0 & ishw[0]) + __popc(k1 & ishw[1])
                                      + __popc(k2 & ishw[2]) + __popc(k3 & ishw[3]);
                        slot = (nhT < MAX_H ? nhT : MAX_H) + ro;
                    }
                }
                if (slot >= 0) {
                    coords[slot] = sb[tid];
                    labp[slot]   = sl[tid];
                    scp[slot]    = ss[tid];
                }
            }
        }
    }
    __syncthreads();

    const int nh = s_nh;
    const int nt = s_nt;

    // ---- phase 6: per-slot GT-match bitmasks and s^p ----
    if (tid < NMAX) {
        unsigned bh = 0, bo = 0;
        float pwv = 0.0f;
        if (tid < nt) {
            const float4 c = coords[tid];
            #pragma unroll
            for (int t = 0; t < TT; t++) {
                if (iou_ge(c, stbh[t], 0.5f)) bh |= (1u << t);
                if (iou_ge(c, stbo[t], 0.5f)) bo |= (1u << t);
            }
            pwv = __powf(scp[tid], PEXP);
        }
        mbits_h[tid] = bh;
        mbits_o[tid] = bo;
        pw[tid] = pwv;
    }
    __syncthreads();

    // ---- phase 7: small outputs + compact valid-pair lists ----
    for (int m = tid; m < MM; m += 256) {
        const int x = m / NMAX;
        const int y = m - x * NMAX;
        const bool pv = (x < nh) && (y < nt) && (x != y);
        float4 bh = make_float4(0.f, 0.f, 0.f, 0.f);
        float4 bo = bh;
        int cls = 0;
        if (pv) {
            bh = coords[x];
            bo = coords[y];
            cls = labp[y];
            const unsigned mask = mbits_h[x] & mbits_o[y];
            const int slot = atomicAdd(&s_cnt, 1);
            g_list[b][slot] = make_uint4((unsigned)m | (mask << 16),
                                         (unsigned)cls,
                                         __float_as_uint(pw[x]),
                                         __float_as_uint(pw[y]));
        }
        const int row = b * MM + m;
        ((float4*)(out + OFF_BH))[row] = bh;
        ((float4*)(out + OFF_BO))[row] = bo;
        (out + OFF_CLS)[row] = pv ? (float)cls : 0.0f;
        (out + OFF_PV)[row]  = pv ? 1.0f : 0.0f;
    }
    __syncthreads();
    if (tid == 0) g_cnt[b] = s_cnt;
}

// ============================================================
// Kernel 2: expansion of valid rows only. 256 blocks =
// 4 blocks per image x 8 warps = 32 warps per image;
// each valid row fully overwritten (lab + prior0 + prior1).
// ============================================================
__global__ __launch_bounds__(256, 8)
void pairgen_expand_kernel(const int* __restrict__ gt_labels,
                           const float* __restrict__ mapping,
                           float* __restrict__ out) {
    const int img  = blockIdx.x & 63;
    const int part = blockIdx.x >> 6;       // 0..3
    const int tid  = threadIdx.x;
    const int wid  = tid >> 5;
    const int lane = tid & 31;

    __shared__ int sgt[TT];
    __shared__ unsigned int bmp[8][20];
    if (tid < TT) sgt[tid] = gt_labels[img * TT + tid];
    __syncthreads();

    const int cnt = g_cnt[img];
    for (int k = part * 8 + wid; k < cnt; k += 32) {
        const uint4 e = g_list[img][k];
        const int m = (int)(e.x & 0xffffu);
        const unsigned mask = e.x >> 16;
        const int cls = (int)e.y;
        const float sh = __uint_as_float(e.z);
        const float so = __uint_as_float(e.w);
        const int row = img * MM + m;

        float4* lab = (float4*)(out + OFF_LAB) + (size_t)row * 150;
        float4* pr0 = (float4*)(out + OFF_PRI) + ((size_t)img * 2 * MM + m) * 150;
        float4* pr1 = pr0 + (size_t)MM * 150;

        if (lane < 19) bmp[wid][lane] = 0;
        __syncwarp();
        if (lane < TT && ((mask >> lane) & 1u)) {
            const int c = sgt[lane];
            atomicOr(&bmp[wid][c >> 5], 1u << (c & 31));
        }
        __syncwarp();

        const float4* mr = (const float4*)(mapping + cls * NUM_CLS);
        for (int i = lane; i < 150; i += 32) {
            const float4 mv = mr[i];
            pr0[i] = make_float4(mv.x * sh, mv.y * sh, mv.z * sh, mv.w * sh);
            pr1[i] = make_float4(mv.x * so, mv.y * so, mv.z * so, mv.w * so);
            const int c = i * 4;
            float4 lv;
            lv.x = ((bmp[wid][(c + 0) >> 5] >> ((c + 0) & 31)) & 1u) ? 1.0f : 0.0f;
            lv.y = ((bmp[wid][(c + 1) >> 5] >> ((c + 1) & 31)) & 1u) ? 1.0f : 0.0f;
            lv.z = ((bmp[wid][(c + 2) >> 5] >> ((c + 2) & 31)) & 1u) ? 1.0f : 0.0f;
            lv.w = ((bmp[wid][(c + 3) >> 5] >> ((c + 3) & 31)) & 1u) ? 1.0f : 0.0f;
            lab[i] = lv;
        }
        __syncwarp();
    }
}

extern "C" void kernel_launch(void* const* d_in, const int* in_sizes, int n_in,
                              void* d_out, int out_size) {
    const float* boxes     = (const float*)d_in[0];
    const float* scores    = (const float*)d_in[1];
    const int*   labels    = (const int*)  d_in[2];
    const float* t_boxes_h = (const float*)d_in[3];
    const float* t_boxes_o = (const float*)d_in[4];
    const int*   gt_labels = (const int*)  d_in[5];
    const float* mapping   = (const float*)d_in[6];
    float* out = (float*)d_out;

    pairgen_fused_kernel<<<K1_BLOCKS, 256>>>(boxes, scores, labels,
                                             t_boxes_h, t_boxes_o, out);
    pairgen_expand_kernel<<<256, 256>>>(gt_labels, mapping, out);
}